// round 11
// baseline (speedup 1.0000x reference)
#include <cuda_runtime.h>
#include <cuda_fp16.h>

#define NUSERS 100000
#define NITEMS 50000
#define DIM 64
#define NNODES 150001            // users + items + padding row
#define ND 9600064               // NNODES * DIM
#define NEDGES 4800000

#define SCAN_CHUNK 512
#define NB_SCAN ((NNODES + SCAN_CHUNK - 1) / SCAN_CHUNK)   // 293
#define NZERO4 ((NNODES + 3) / 4)                           // 37501 int4 stores
#define EDGE_BATCH 4
#define NEB (NEDGES / EDGE_BATCH)

// ---------------- device scratch (static allocation — allowed) -------------
__device__ int   g_idx_stride;            // 2 if int64 indices, 1 if int32
__device__ int   g_counts[NNODES + 15];   // row degrees
__device__ int   g_rowptr[NNODES];        // row start slots (non-monotonic ok)
__device__ int   g_cursor[NNODES];        // scatter cursors
__device__ int   g_total;                 // block-base reservation counter
__device__ int2  g_edges[NEDGES];         // packed CSR records: col, bits(val)
__device__ uint2 g_mir0[ND / 4];          // fp16 mirror ping: 16 uint2 per row
__device__ uint2 g_mir1[ND / 4];          // fp16 mirror pong

// ---------------------------------------------------------------------------
// Launch 0: zero counters + total + (thread 0) detect index width.
// ---------------------------------------------------------------------------
__global__ void gcn_zero_detect(const int* __restrict__ rows32,
                                const int* __restrict__ cols32) {
    int i = blockIdx.x * blockDim.x + threadIdx.x;
    if (i < NZERO4)
        reinterpret_cast<int4*>(g_counts)[i] = make_int4(0, 0, 0, 0);
    if (i == 0) {
        g_total = 0;
        bool is64 = true;
        #pragma unroll
        for (int k = 0; k < 16; k++) {
            if (rows32[2 * k + 1] != 0) is64 = false;
            if (cols32[2 * k + 1] != 0) is64 = false;
        }
        g_idx_stride = is64 ? 2 : 1;
    }
}

// ---------------------------------------------------------------------------
// Launch 1: ego = concat(user_emb, item_emb) in f32 + fp16 mirror (ping).
// ---------------------------------------------------------------------------
__global__ void gcn_init_kernel(const float4* __restrict__ user_emb,
                                const float4* __restrict__ item_emb,
                                float4* __restrict__ ego) {
    const int n4 = ND / 4;
    const int u4 = NUSERS * (DIM / 4);
    int i = blockIdx.x * blockDim.x + threadIdx.x;
    if (i < n4) {
        float4 v = (i < u4) ? user_emb[i] : item_emb[i - u4];
        ego[i] = v;
        uint2 o;
        __half2 p0 = __floats2half2_rn(v.x, v.y);
        __half2 p1 = __floats2half2_rn(v.z, v.w);
        o.x = *reinterpret_cast<unsigned*>(&p0);
        o.y = *reinterpret_cast<unsigned*>(&p1);
        g_mir0[i] = o;
    }
}

// ---------------------------------------------------------------------------
// Launch 2: histogram of row degrees (4 edges/thread).
// ---------------------------------------------------------------------------
__global__ void gcn_hist_kernel(const int* __restrict__ rowsw) {
    int t = blockIdx.x * blockDim.x + threadIdx.x;
    if (t >= NEB) return;
    int e = t * EDGE_BATCH;
    int stride = g_idx_stride;
    int r0 = rowsw[(e + 0) * stride];
    int r1 = rowsw[(e + 1) * stride];
    int r2 = rowsw[(e + 2) * stride];
    int r3 = rowsw[(e + 3) * stride];
    atomicAdd(&g_counts[r0], 1);
    atomicAdd(&g_counts[r1], 1);
    atomicAdd(&g_counts[r2], 1);
    atomicAdd(&g_counts[r3], 1);
}

// ---------------------------------------------------------------------------
// Launch 3: fused scan (block scan + atomic base reservation).
// ---------------------------------------------------------------------------
__global__ void gcn_scan_fused(void) {
    __shared__ int s[SCAN_CHUNK];
    __shared__ int base_sh;
    int t = threadIdx.x;
    int i = blockIdx.x * SCAN_CHUNK + t;
    int x = (i < NNODES) ? g_counts[i] : 0;
    s[t] = x;
    __syncthreads();
    for (int off = 1; off < SCAN_CHUNK; off <<= 1) {
        int v = (t >= off) ? s[t - off] : 0;
        __syncthreads();
        s[t] += v;
        __syncthreads();
    }
    if (t == SCAN_CHUNK - 1)
        base_sh = atomicAdd(&g_total, s[SCAN_CHUNK - 1]);
    __syncthreads();
    if (i < NNODES) {
        int start = base_sh + s[t] - x;
        g_rowptr[i] = start;
        g_cursor[i] = start;
    }
}

// ---------------------------------------------------------------------------
// Launch 4: scatter edges into packed CSR slots (1 edge/thread — measured
// faster than 4/thread: the kernel is wavefront-floor-bound, not latency).
// ---------------------------------------------------------------------------
__global__ void gcn_scatter_kernel(const int* __restrict__ rowsw,
                                   const int* __restrict__ colsw,
                                   const float* __restrict__ vals) {
    int e = blockIdx.x * blockDim.x + threadIdx.x;
    if (e < NEDGES) {
        int stride = g_idx_stride;
        int r = rowsw[e * stride];
        int c = colsw[e * stride];
        float v = vals[e];
        int pos = atomicAdd(&g_cursor[r], 1);
        g_edges[pos] = make_int2(c, __float_as_int(v));
    }
}

// ---------------------------------------------------------------------------
// Launches 5-7: half-warp-split CSR SpMM.
// Lanes 0-15 process the first half of the edge list, lanes 16-31 the second
// — two independent gather chains per warp (2x MLP), 16-wide shfl broadcast.
// Each lane covers 4 dims (uint2 = 2x half2). Cross-half combine via
// shfl_xor(16). Epilogue split: half 0 writes f32 y, half 1 writes the fp16
// mirror (or the fused hsum).
// ---------------------------------------------------------------------------
template <bool FUSE>
__global__ void __launch_bounds__(256)
gcn_spmm_h(int srcSel,
           float* __restrict__ y,
           const float* __restrict__ ego,
           const float* __restrict__ h1,
           const float* __restrict__ h2,
           float* __restrict__ hsum) {
    int warp = (blockIdx.x * blockDim.x + threadIdx.x) >> 5;
    if (warp >= NNODES) return;
    int lane = threadIdx.x & 31;
    int g    = lane >> 4;                 // half-warp id
    int sub  = lane & 15;
    unsigned gmask = g ? 0xffff0000u : 0x0000ffffu;

    const uint2* __restrict__ hin  = srcSel ? g_mir1 : g_mir0;
    uint2* __restrict__       hout = srcSel ? g_mir0 : g_mir1;

    int start = __ldg(&g_rowptr[warp]);
    int cnt   = __ldg(&g_counts[warp]);
    int h     = (cnt + 1) >> 1;           // split point
    int gstart = start + g * h;
    int gcnt   = g ? (cnt - h) : h;

    float a0 = 0.f, a1 = 0.f, a2 = 0.f, a3 = 0.f;

    for (int base = 0; base < gcnt; base += 16) {
        int m = base + sub;
        int2 my = (m < gcnt) ? g_edges[gstart + m] : make_int2(0, 0);
        int kmax = gcnt - base; if (kmax > 16) kmax = 16;
        #pragma unroll 4
        for (int k = 0; k < kmax; k++) {
            int   c = __shfl_sync(gmask, my.x, k, 16);
            float v = __int_as_float(__shfl_sync(gmask, my.y, k, 16));
            uint2 q = hin[(size_t)c * 16 + sub];
            __half2 q0 = *reinterpret_cast<__half2*>(&q.x);
            __half2 q1 = *reinterpret_cast<__half2*>(&q.y);
            float2 f0 = __half22float2(q0);
            float2 f1 = __half22float2(q1);
            a0 += v * f0.x; a1 += v * f0.y;
            a2 += v * f1.x; a3 += v * f1.y;
        }
    }

    // combine the two half-warps (both halves converged here)
    a0 += __shfl_xor_sync(0xffffffffu, a0, 16);
    a1 += __shfl_xor_sync(0xffffffffu, a1, 16);
    a2 += __shfl_xor_sync(0xffffffffu, a2, 16);
    a3 += __shfl_xor_sync(0xffffffffu, a3, 16);

    size_t nbase = (size_t)warp * DIM + sub * 4;
    if (g == 0) {
        *reinterpret_cast<float4*>(y + nbase) = make_float4(a0, a1, a2, a3);
    } else if (FUSE) {
        float4 a = *reinterpret_cast<const float4*>(ego + nbase);
        float4 b = *reinterpret_cast<const float4*>(h1 + nbase);
        float4 c = *reinterpret_cast<const float4*>(h2 + nbase);
        *reinterpret_cast<float4*>(hsum + nbase) =
            make_float4(a.x + b.x + c.x + a0, a.y + b.y + c.y + a1,
                        a.z + b.z + c.z + a2, a.w + b.w + c.w + a3);
    } else {
        uint2 o;
        __half2 p0 = __floats2half2_rn(a0, a1);
        __half2 p1 = __floats2half2_rn(a2, a3);
        o.x = *reinterpret_cast<unsigned*>(&p0);
        o.y = *reinterpret_cast<unsigned*>(&p1);
        hout[(size_t)warp * 16 + sub] = o;
    }
}

// ---------------------------------------------------------------------------
// kernel_launch — graph-capturable, allocation-free.
// Output layout (out_size = 5*ND): [h_sum | ego | h1 | h2 | h3]
// ---------------------------------------------------------------------------
extern "C" void kernel_launch(void* const* d_in, const int* in_sizes, int n_in,
                              void* d_out, int out_size) {
    const float* user_emb = (const float*)d_in[0];
    const float* item_emb = (const float*)d_in[1];
    const float* vals     = (const float*)d_in[2];
    const int*   rowsw    = (const int*)d_in[3];
    const int*   colsw    = (const int*)d_in[4];

    float* out  = (float*)d_out;
    float* hsum = out;
    float* ego  = out + (size_t)ND;
    float* h1   = out + (size_t)2 * ND;
    float* h2   = out + (size_t)3 * ND;
    float* h3   = out + (size_t)4 * ND;

    // 0
    gcn_zero_detect<<<(NZERO4 + 255) / 256, 256>>>(rowsw, colsw);
    // 1
    {
        const int n4 = ND / 4;
        gcn_init_kernel<<<(n4 + 255) / 256, 256>>>(
            (const float4*)user_emb, (const float4*)item_emb, (float4*)ego);
    }
    // 2
    gcn_hist_kernel<<<(NEB + 255) / 256, 256>>>(rowsw);
    // 3
    gcn_scan_fused<<<NB_SCAN, SCAN_CHUNK>>>();
    // 4
    gcn_scatter_kernel<<<(NEDGES + 255) / 256, 256>>>(rowsw, colsw, vals);
    // 5-7
    {
        long long threads = (long long)NNODES * 32;
        unsigned grd = (unsigned)((threads + 255) / 256);
        gcn_spmm_h<false><<<grd, 256>>>(0, h1, nullptr, nullptr, nullptr,
                                        nullptr);   // mir0 -> h1, mir1
        gcn_spmm_h<false><<<grd, 256>>>(1, h2, nullptr, nullptr, nullptr,
                                        nullptr);   // mir1 -> h2, mir0
        gcn_spmm_h<true><<<grd, 256>>>(0, h3, ego, h1, h2, hsum);  // mir0 -> h3
    }
}